// round 9
// baseline (speedup 1.0000x reference)
#include <cuda_runtime.h>
#include <cstdint>

// ----------------------------------------------------------------------------
// WindowAttention: 2048 windows x 8 heads, M=N=64, D=64, fp32.
// One CTA per (b,h); 64 threads / 2 warps; each warp owns 32 query rows
// (two m16 tiles) so every K/V B-fragment load feeds 4 HMMAs.
// Q/K/V arrive via cp.async (raw fp32). K,V fed directly to HMMA.TF32
// (hardware uses upper 19 bits). Q and P are exactly split to tf32 hi+lo.
// Bias pre-laid-out in fragment order. Coalesced rolled output stores.
// ----------------------------------------------------------------------------

#define QSTRIDE 68                    // mod 32 == 4 -> conflict-free frag reads
#define KSTRIDE 68
#define VSTRIDE 72                    // mod 32 == 8 -> conflict-free V frags
#define SQ_FLOATS (64 * QSTRIDE)      // 4352 (Q raw -> P -> O stage)
#define SK_FLOATS (64 * KSTRIDE)      // 4352 (K raw)
#define SV_FLOATS (64 * VSTRIDE)      // 4608 (V raw)
#define SCALE_L2E 0.1803368801111146f // 0.125 * log2(e)

// bias fragment order: [h][blk16][n][lane] float4 =
//   { b[rA][8n+2tig], b[rA][8n+2tig+1], b[rA+8][8n+2tig], b[rA+8][8n+2tig+1] } * log2e
// rA = 16*blk + (lane>>2).  8*4*8*32 float4 = 128 KB, L2-resident.
__device__ float4 g_biasF[8 * 4 * 8 * 32];

__global__ void bias_precompute_kernel(const float* __restrict__ table) {
    int t = blockIdx.x * blockDim.x + threadIdx.x;   // 0..8191
    if (t >= 8192) return;
    int h = t >> 10, blk = (t >> 8) & 3, n = (t >> 5) & 7, lane = t & 31;
    int g = lane >> 2, tig = lane & 3;
    int rA = 16 * blk + g, rB = rA + 8;
    int col = 8 * n + 2 * tig;
    const float L2E = 1.4426950408889634f;
    float4 r;
#define BIAS_AT(rr, cc, dst) {                                   \
        int raw = ((rr) - 32) * 128 + ((cc) - 32) + 64;          \
        int idx = raw < 0 ? raw + 16129 : raw;                   \
        dst = table[(size_t)idx * 8 + h] * L2E; }
    BIAS_AT(rA, col,     r.x);
    BIAS_AT(rA, col + 1, r.y);
    BIAS_AT(rB, col,     r.z);
    BIAS_AT(rB, col + 1, r.w);
#undef BIAS_AT
    g_biasF[t] = r;
}

__device__ __forceinline__ uint32_t f2tf32(float x) {
    uint32_t r;
    asm("cvt.rna.tf32.f32 %0, %1;" : "=r"(r) : "f"(x));
    return r;
}

__device__ __forceinline__ void split_tf32(float x, uint32_t& hi, uint32_t& lo) {
    hi = f2tf32(x);
    lo = f2tf32(x - __uint_as_float(hi));
}

__device__ __forceinline__ void mma_tf32(float c[4],
                                         uint32_t a0, uint32_t a1, uint32_t a2, uint32_t a3,
                                         uint32_t b0, uint32_t b1) {
    asm volatile(
        "mma.sync.aligned.m16n8k8.row.col.f32.tf32.tf32.f32 "
        "{%0,%1,%2,%3}, {%4,%5,%6,%7}, {%8,%9}, {%0,%1,%2,%3};"
        : "+f"(c[0]), "+f"(c[1]), "+f"(c[2]), "+f"(c[3])
        : "r"(a0), "r"(a1), "r"(a2), "r"(a3), "r"(b0), "r"(b1));
}

__device__ __forceinline__ void cp16(uint32_t smem_dst, const void* gmem_src) {
    asm volatile("cp.async.cg.shared.global [%0], [%1], 16;"
                 :: "r"(smem_dst), "l"(gmem_src));
}

__global__ __launch_bounds__(64) void winattn_kernel(
    const float* __restrict__ q, const float* __restrict__ k,
    const float* __restrict__ v, float* __restrict__ out) {
    extern __shared__ float smem[];
    float* sQ = smem;                    // raw Q -> P buffer -> O stage
    float* sK = smem + SQ_FLOATS;        // raw K
    float* sV = smem + SQ_FLOATS + SK_FLOATS;  // raw V

    const int bh   = blockIdx.x;
    const int b    = bh >> 3;
    const int h    = bh & 7;
    const int tid  = threadIdx.x;
    const int lane = tid & 31;
    const int g    = lane >> 2;          // 0..7
    const int tig  = lane & 3;           // 0..3
    const int w    = tid >> 5;           // warp 0/1
    const int r0   = w * 32;             // warp's first query row (32 rows)

    // ---- async one-pass staging of raw Q, K, V ------------------------------
    {
        const float4* qg = (const float4*)(q + (size_t)bh * 4096);
        const float4* kg = (const float4*)(k + (size_t)bh * 4096);
        const float4* vg = (const float4*)(v + (size_t)bh * 4096);
        uint32_t sQu = (uint32_t)__cvta_generic_to_shared(sQ);
        uint32_t sKu = (uint32_t)__cvta_generic_to_shared(sK);
        uint32_t sVu = (uint32_t)__cvta_generic_to_shared(sV);
#pragma unroll
        for (int j = 0; j < 16; ++j) {
            int i = tid + 64 * j;
            int m = i >> 4, c4 = i & 15;
            cp16(sQu + (m * QSTRIDE + c4 * 4) * 4, qg + i);
            cp16(sKu + (m * KSTRIDE + c4 * 4) * 4, kg + i);
            cp16(sVu + (m * VSTRIDE + c4 * 4) * 4, vg + i);
        }
        asm volatile("cp.async.commit_group;");
        asm volatile("cp.async.wait_group 0;" ::: "memory");
    }
    __syncthreads();

    // ---- S = Q K^T : Q exact (hi+lo), K raw fp32 as tf32 --------------------
    float c0[8][4], c1[8][4];
#pragma unroll
    for (int n = 0; n < 8; ++n) {
#pragma unroll
        for (int j = 0; j < 4; ++j) { c0[n][j] = 0.f; c1[n][j] = 0.f; }
    }

#pragma unroll
    for (int ks = 0; ks < 8; ++ks) {
        const int kc = ks * 8 + tig;
        // tile0 rows r0+g, r0+g+8 ; tile1 rows r0+g+16, r0+g+24
        uint32_t ha0, la0, ha1, la1, ha2, la2, ha3, la3;
        uint32_t hc0, lc0, hc1, lc1, hc2, lc2, hc3, lc3;
        split_tf32(sQ[(r0 + g) * QSTRIDE + kc],          ha0, la0);
        split_tf32(sQ[(r0 + g + 8) * QSTRIDE + kc],      ha1, la1);
        split_tf32(sQ[(r0 + g) * QSTRIDE + kc + 4],      ha2, la2);
        split_tf32(sQ[(r0 + g + 8) * QSTRIDE + kc + 4],  ha3, la3);
        split_tf32(sQ[(r0 + g + 16) * QSTRIDE + kc],     hc0, lc0);
        split_tf32(sQ[(r0 + g + 24) * QSTRIDE + kc],     hc1, lc1);
        split_tf32(sQ[(r0 + g + 16) * QSTRIDE + kc + 4], hc2, lc2);
        split_tf32(sQ[(r0 + g + 24) * QSTRIDE + kc + 4], hc3, lc3);
#pragma unroll
        for (int n = 0; n < 8; ++n) {
            uint32_t b0 = __float_as_uint(sK[(n * 8 + g) * KSTRIDE + kc]);
            uint32_t b1 = __float_as_uint(sK[(n * 8 + g) * KSTRIDE + kc + 4]);
            mma_tf32(c0[n], ha0, ha1, ha2, ha3, b0, b1);
            mma_tf32(c0[n], la0, la1, la2, la3, b0, b1);
            mma_tf32(c1[n], hc0, hc1, hc2, hc3, b0, b1);
            mma_tf32(c1[n], lc0, lc1, lc2, lc3, b0, b1);
        }
    }

    // ---- scale + bias (fragment-order, coalesced, L2-resident) --------------
    {
        const float4* bf0 = g_biasF + ((h * 4 + 2 * w) * 8) * 32 + lane;
        const float4* bf1 = bf0 + 8 * 32;
#pragma unroll
        for (int n = 0; n < 8; ++n) {
            float4 b0 = bf0[n * 32];
            float4 b1 = bf1[n * 32];
            c0[n][0] = fmaf(c0[n][0], SCALE_L2E, b0.x);
            c0[n][1] = fmaf(c0[n][1], SCALE_L2E, b0.y);
            c0[n][2] = fmaf(c0[n][2], SCALE_L2E, b0.z);
            c0[n][3] = fmaf(c0[n][3], SCALE_L2E, b0.w);
            c1[n][0] = fmaf(c1[n][0], SCALE_L2E, b1.x);
            c1[n][1] = fmaf(c1[n][1], SCALE_L2E, b1.y);
            c1[n][2] = fmaf(c1[n][2], SCALE_L2E, b1.z);
            c1[n][3] = fmaf(c1[n][3], SCALE_L2E, b1.w);
        }
    }

    // ---- softmax (base-2 domain; quad holds a full row; 4 row-groups) -------
    float mx0 = -1e30f, mx1 = -1e30f, mx2 = -1e30f, mx3 = -1e30f;
#pragma unroll
    for (int n = 0; n < 8; ++n) {
        mx0 = fmaxf(mx0, fmaxf(c0[n][0], c0[n][1]));
        mx1 = fmaxf(mx1, fmaxf(c0[n][2], c0[n][3]));
        mx2 = fmaxf(mx2, fmaxf(c1[n][0], c1[n][1]));
        mx3 = fmaxf(mx3, fmaxf(c1[n][2], c1[n][3]));
    }
#pragma unroll
    for (int d = 1; d <= 2; d <<= 1) {
        mx0 = fmaxf(mx0, __shfl_xor_sync(0xffffffffu, mx0, d));
        mx1 = fmaxf(mx1, __shfl_xor_sync(0xffffffffu, mx1, d));
        mx2 = fmaxf(mx2, __shfl_xor_sync(0xffffffffu, mx2, d));
        mx3 = fmaxf(mx3, __shfl_xor_sync(0xffffffffu, mx3, d));
    }

    float s0 = 0.f, s1 = 0.f, s2 = 0.f, s3 = 0.f;
#pragma unroll
    for (int n = 0; n < 8; ++n) {
        c0[n][0] = exp2f(c0[n][0] - mx0);
        c0[n][1] = exp2f(c0[n][1] - mx0);
        c0[n][2] = exp2f(c0[n][2] - mx1);
        c0[n][3] = exp2f(c0[n][3] - mx1);
        c1[n][0] = exp2f(c1[n][0] - mx2);
        c1[n][1] = exp2f(c1[n][1] - mx2);
        c1[n][2] = exp2f(c1[n][2] - mx3);
        c1[n][3] = exp2f(c1[n][3] - mx3);
        s0 += c0[n][0] + c0[n][1];
        s1 += c0[n][2] + c0[n][3];
        s2 += c1[n][0] + c1[n][1];
        s3 += c1[n][2] + c1[n][3];
    }
#pragma unroll
    for (int d = 1; d <= 2; d <<= 1) {
        s0 += __shfl_xor_sync(0xffffffffu, s0, d);
        s1 += __shfl_xor_sync(0xffffffffu, s1, d);
        s2 += __shfl_xor_sync(0xffffffffu, s2, d);
        s3 += __shfl_xor_sync(0xffffffffu, s3, d);
    }
    float inv0 = 1.0f / s0, inv1 = 1.0f / s1;
    float inv2 = 1.0f / s2, inv3 = 1.0f / s3;

    // ---- stage unnormalized P over sQ (warp-private rows) -------------------
    float* sP = sQ;
#pragma unroll
    for (int n = 0; n < 8; ++n) {
        int col = n * 8 + 2 * tig;
        *(float2*)(sP + (r0 + g) * QSTRIDE + col)      = make_float2(c0[n][0], c0[n][1]);
        *(float2*)(sP + (r0 + g + 8) * QSTRIDE + col)  = make_float2(c0[n][2], c0[n][3]);
        *(float2*)(sP + (r0 + g + 16) * QSTRIDE + col) = make_float2(c1[n][0], c1[n][1]);
        *(float2*)(sP + (r0 + g + 24) * QSTRIDE + col) = make_float2(c1[n][2], c1[n][3]);
    }
    __syncwarp();

    // ---- O = P V : P exact (hi+lo), V raw fp32 as tf32 ----------------------
    float o0[8][4], o1[8][4];
#pragma unroll
    for (int d = 0; d < 8; ++d) {
#pragma unroll
        for (int j = 0; j < 4; ++j) { o0[d][j] = 0.f; o1[d][j] = 0.f; }
    }

#pragma unroll
    for (int ks = 0; ks < 8; ++ks) {
        const int kc = ks * 8 + tig;
        uint32_t ha0, la0, ha1, la1, ha2, la2, ha3, la3;
        uint32_t hc0, lc0, hc1, lc1, hc2, lc2, hc3, lc3;
        split_tf32(sP[(r0 + g) * QSTRIDE + kc],          ha0, la0);
        split_tf32(sP[(r0 + g + 8) * QSTRIDE + kc],      ha1, la1);
        split_tf32(sP[(r0 + g) * QSTRIDE + kc + 4],      ha2, la2);
        split_tf32(sP[(r0 + g + 8) * QSTRIDE + kc + 4],  ha3, la3);
        split_tf32(sP[(r0 + g + 16) * QSTRIDE + kc],     hc0, lc0);
        split_tf32(sP[(r0 + g + 24) * QSTRIDE + kc],     hc1, lc1);
        split_tf32(sP[(r0 + g + 16) * QSTRIDE + kc + 4], hc2, lc2);
        split_tf32(sP[(r0 + g + 24) * QSTRIDE + kc + 4], hc3, lc3);
#pragma unroll
        for (int dt = 0; dt < 8; ++dt) {
            uint32_t b0 = __float_as_uint(sV[(ks * 8 + tig) * VSTRIDE + dt * 8 + g]);
            uint32_t b1 = __float_as_uint(sV[(ks * 8 + tig + 4) * VSTRIDE + dt * 8 + g]);
            mma_tf32(o0[dt], ha0, ha1, ha2, ha3, b0, b1);
            mma_tf32(o0[dt], la0, la1, la2, la3, b0, b1);
            mma_tf32(o1[dt], hc0, hc1, hc2, hc3, b0, b1);
            mma_tf32(o1[dt], lc0, lc1, lc2, lc3, b0, b1);
        }
    }

    // ---- stage normalized O over sP (warp-private rows) ---------------------
    __syncwarp();             // all lanes of this warp finished reading sP rows
    float* sO = sQ;
#pragma unroll
    for (int dt = 0; dt < 8; ++dt) {
        int col = dt * 8 + 2 * tig;
        *(float2*)(sO + (r0 + g) * QSTRIDE + col)      = make_float2(o0[dt][0] * inv0, o0[dt][1] * inv0);
        *(float2*)(sO + (r0 + g + 8) * QSTRIDE + col)  = make_float2(o0[dt][2] * inv1, o0[dt][3] * inv1);
        *(float2*)(sO + (r0 + g + 16) * QSTRIDE + col) = make_float2(o1[dt][0] * inv2, o1[dt][1] * inv2);
        *(float2*)(sO + (r0 + g + 24) * QSTRIDE + col) = make_float2(o1[dt][2] * inv3, o1[dt][3] * inv3);
    }
    __syncthreads();

    // out[b*32768 + row*512 + ((h*64 + d - 32) & 511)], row-contiguous float4
    {
        float* ob = out + (size_t)b * 32768;
        const int cbase = h * 64 - 32;
        const int c4 = tid & 15;            // 16 float4 per row
        const int col = (cbase + 4 * c4) & 511;
#pragma unroll
        for (int it = 0; it < 16; ++it) {
            int row = (tid >> 4) + 4 * it;
            float4 val = *(const float4*)(sO + row * QSTRIDE + c4 * 4);
            *(float4*)(ob + row * 512 + col) = val;
        }
    }
}

extern "C" void kernel_launch(void* const* d_in, const int* in_sizes, int n_in,
                              void* d_out, int out_size) {
    const float* q     = (const float*)d_in[0];
    const float* k     = (const float*)d_in[1];
    const float* v     = (const float*)d_in[2];
    const float* table = (const float*)d_in[3];
    float* out = (float*)d_out;

    bias_precompute_kernel<<<32, 256>>>(table);

    const int smem_bytes = (SQ_FLOATS + SK_FLOATS + SV_FLOATS) * sizeof(float); // 53248 B
    cudaFuncSetAttribute(winattn_kernel,
                         cudaFuncAttributeMaxDynamicSharedMemorySize, smem_bytes);
    winattn_kernel<<<16384, 64, smem_bytes>>>(q, k, v, out);
}

// round 10
// speedup vs baseline: 1.1358x; 1.1358x over previous
#include <cuda_runtime.h>
#include <cstdint>

// ----------------------------------------------------------------------------
// WindowAttention: 2048 windows x 8 heads, M=N=64, D=64, fp32.
// One CTA per (b,h); 64 threads / 2 warps; each warp owns 32 query rows
// (two m16 tiles) so every K/V B-fragment load feeds 4 HMMAs.
// Smem time-multiplex: [sQ: Q -> P -> O] [sKV: K -> V] = 35.8 KB -> 6 CTAs/SM.
// V is cp.async'd into the K region after the QK mainloop, hidden behind
// bias + softmax + P staging. K/V raw fp32 fed to HMMA.TF32; Q,P exact hi+lo.
// ----------------------------------------------------------------------------

#define QSTRIDE 68                    // mod 32 == 4 -> bank 4g+tig, conflict-free
#define KSTRIDE 68                    // same region as V, K laid at stride 68
#define VSTRIDE 72                    // mod 32 == 8 -> bank 8tig+g, conflict-free
#define SQ_FLOATS (64 * QSTRIDE)      // 17408 B (Q raw -> P -> O stage)
#define SKV_FLOATS (64 * VSTRIDE)     // 18432 B (K raw, then V raw)
#define SCALE_L2E 0.1803368801111146f // 0.125 * log2(e)

// bias fragment order: [h][blk16][n][lane] float4 =
//   { b[rA][8n+2tig], b[rA][8n+2tig+1], b[rA+8][8n+2tig], b[rA+8][8n+2tig+1] } * log2e
// rA = 16*blk + (lane>>2).  8*4*8*32 float4 = 128 KB, L2-resident.
__device__ float4 g_biasF[8 * 4 * 8 * 32];

__global__ void bias_precompute_kernel(const float* __restrict__ table) {
    int t = blockIdx.x * blockDim.x + threadIdx.x;   // 0..8191
    if (t >= 8192) return;
    int h = t >> 10, blk = (t >> 8) & 3, n = (t >> 5) & 7, lane = t & 31;
    int g = lane >> 2, tig = lane & 3;
    int rA = 16 * blk + g, rB = rA + 8;
    int col = 8 * n + 2 * tig;
    const float L2E = 1.4426950408889634f;
    float4 r;
#define BIAS_AT(rr, cc, dst) {                                   \
        int raw = ((rr) - 32) * 128 + ((cc) - 32) + 64;          \
        int idx = raw < 0 ? raw + 16129 : raw;                   \
        dst = table[(size_t)idx * 8 + h] * L2E; }
    BIAS_AT(rA, col,     r.x);
    BIAS_AT(rA, col + 1, r.y);
    BIAS_AT(rB, col,     r.z);
    BIAS_AT(rB, col + 1, r.w);
#undef BIAS_AT
    g_biasF[t] = r;
}

__device__ __forceinline__ uint32_t f2tf32(float x) {
    uint32_t r;
    asm("cvt.rna.tf32.f32 %0, %1;" : "=r"(r) : "f"(x));
    return r;
}

__device__ __forceinline__ void split_tf32(float x, uint32_t& hi, uint32_t& lo) {
    hi = f2tf32(x);
    lo = f2tf32(x - __uint_as_float(hi));
}

__device__ __forceinline__ void mma_tf32(float c[4],
                                         uint32_t a0, uint32_t a1, uint32_t a2, uint32_t a3,
                                         uint32_t b0, uint32_t b1) {
    asm volatile(
        "mma.sync.aligned.m16n8k8.row.col.f32.tf32.tf32.f32 "
        "{%0,%1,%2,%3}, {%4,%5,%6,%7}, {%8,%9}, {%0,%1,%2,%3};"
        : "+f"(c[0]), "+f"(c[1]), "+f"(c[2]), "+f"(c[3])
        : "r"(a0), "r"(a1), "r"(a2), "r"(a3), "r"(b0), "r"(b1));
}

__device__ __forceinline__ void cp16(uint32_t smem_dst, const void* gmem_src) {
    asm volatile("cp.async.cg.shared.global [%0], [%1], 16;"
                 :: "r"(smem_dst), "l"(gmem_src));
}

__global__ __launch_bounds__(64, 6) void winattn_kernel(
    const float* __restrict__ q, const float* __restrict__ k,
    const float* __restrict__ v, float* __restrict__ out) {
    extern __shared__ float smem[];
    float* sQ  = smem;                   // raw Q -> P buffer -> O stage
    float* sKV = smem + SQ_FLOATS;       // raw K, then raw V

    const int bh   = blockIdx.x;
    const int b    = bh >> 3;
    const int h    = bh & 7;
    const int tid  = threadIdx.x;
    const int lane = tid & 31;
    const int g    = lane >> 2;          // 0..7
    const int tig  = lane & 3;           // 0..3
    const int w    = tid >> 5;           // warp 0/1
    const int r0   = w * 32;             // warp's first query row (32 rows)

    const uint32_t sQu  = (uint32_t)__cvta_generic_to_shared(sQ);
    const uint32_t sKVu = (uint32_t)__cvta_generic_to_shared(sKV);

    // ---- async staging of raw Q, K (V deferred into same region as K) -------
    {
        const float4* qg = (const float4*)(q + (size_t)bh * 4096);
        const float4* kg = (const float4*)(k + (size_t)bh * 4096);
#pragma unroll
        for (int j = 0; j < 16; ++j) {
            int i = tid + 64 * j;
            int m = i >> 4, c4 = i & 15;
            cp16(sQu  + (m * QSTRIDE + c4 * 4) * 4, qg + i);
            cp16(sKVu + (m * KSTRIDE + c4 * 4) * 4, kg + i);
        }
        asm volatile("cp.async.commit_group;");
        asm volatile("cp.async.wait_group 0;" ::: "memory");
    }
    __syncthreads();

    // ---- S = Q K^T : Q exact (hi+lo), K raw fp32 as tf32 --------------------
    float c0[8][4], c1[8][4];
#pragma unroll
    for (int n = 0; n < 8; ++n) {
#pragma unroll
        for (int j = 0; j < 4; ++j) { c0[n][j] = 0.f; c1[n][j] = 0.f; }
    }

#pragma unroll
    for (int ks = 0; ks < 8; ++ks) {
        const int kc = ks * 8 + tig;
        uint32_t ha0, la0, ha1, la1, ha2, la2, ha3, la3;
        uint32_t hc0, lc0, hc1, lc1, hc2, lc2, hc3, lc3;
        split_tf32(sQ[(r0 + g) * QSTRIDE + kc],          ha0, la0);
        split_tf32(sQ[(r0 + g + 8) * QSTRIDE + kc],      ha1, la1);
        split_tf32(sQ[(r0 + g) * QSTRIDE + kc + 4],      ha2, la2);
        split_tf32(sQ[(r0 + g + 8) * QSTRIDE + kc + 4],  ha3, la3);
        split_tf32(sQ[(r0 + g + 16) * QSTRIDE + kc],     hc0, lc0);
        split_tf32(sQ[(r0 + g + 24) * QSTRIDE + kc],     hc1, lc1);
        split_tf32(sQ[(r0 + g + 16) * QSTRIDE + kc + 4], hc2, lc2);
        split_tf32(sQ[(r0 + g + 24) * QSTRIDE + kc + 4], hc3, lc3);
#pragma unroll
        for (int n = 0; n < 8; ++n) {
            uint32_t b0 = __float_as_uint(sKV[(n * 8 + g) * KSTRIDE + kc]);
            uint32_t b1 = __float_as_uint(sKV[(n * 8 + g) * KSTRIDE + kc + 4]);
            mma_tf32(c0[n], ha0, ha1, ha2, ha3, b0, b1);
            mma_tf32(c0[n], la0, la1, la2, la3, b0, b1);
            mma_tf32(c1[n], hc0, hc1, hc2, hc3, b0, b1);
            mma_tf32(c1[n], lc0, lc1, lc2, lc3, b0, b1);
        }
    }

    // ---- K fully consumed: pull V into the same region (async) --------------
    __syncthreads();
    {
        const float4* vg = (const float4*)(v + (size_t)bh * 4096);
#pragma unroll
        for (int j = 0; j < 16; ++j) {
            int i = tid + 64 * j;
            int m = i >> 4, c4 = i & 15;
            cp16(sKVu + (m * VSTRIDE + c4 * 4) * 4, vg + i);
        }
        asm volatile("cp.async.commit_group;");
    }

    // ---- scale + bias (fragment-order, coalesced, L2-resident) --------------
    {
        const float4* bf0 = g_biasF + ((h * 4 + 2 * w) * 8) * 32 + lane;
        const float4* bf1 = bf0 + 8 * 32;
#pragma unroll
        for (int n = 0; n < 8; ++n) {
            float4 b0 = bf0[n * 32];
            float4 b1 = bf1[n * 32];
            c0[n][0] = fmaf(c0[n][0], SCALE_L2E, b0.x);
            c0[n][1] = fmaf(c0[n][1], SCALE_L2E, b0.y);
            c0[n][2] = fmaf(c0[n][2], SCALE_L2E, b0.z);
            c0[n][3] = fmaf(c0[n][3], SCALE_L2E, b0.w);
            c1[n][0] = fmaf(c1[n][0], SCALE_L2E, b1.x);
            c1[n][1] = fmaf(c1[n][1], SCALE_L2E, b1.y);
            c1[n][2] = fmaf(c1[n][2], SCALE_L2E, b1.z);
            c1[n][3] = fmaf(c1[n][3], SCALE_L2E, b1.w);
        }
    }

    // ---- softmax (base-2 domain; quad holds a full row; 4 row-groups) -------
    float mx0 = -1e30f, mx1 = -1e30f, mx2 = -1e30f, mx3 = -1e30f;
#pragma unroll
    for (int n = 0; n < 8; ++n) {
        mx0 = fmaxf(mx0, fmaxf(c0[n][0], c0[n][1]));
        mx1 = fmaxf(mx1, fmaxf(c0[n][2], c0[n][3]));
        mx2 = fmaxf(mx2, fmaxf(c1[n][0], c1[n][1]));
        mx3 = fmaxf(mx3, fmaxf(c1[n][2], c1[n][3]));
    }
#pragma unroll
    for (int d = 1; d <= 2; d <<= 1) {
        mx0 = fmaxf(mx0, __shfl_xor_sync(0xffffffffu, mx0, d));
        mx1 = fmaxf(mx1, __shfl_xor_sync(0xffffffffu, mx1, d));
        mx2 = fmaxf(mx2, __shfl_xor_sync(0xffffffffu, mx2, d));
        mx3 = fmaxf(mx3, __shfl_xor_sync(0xffffffffu, mx3, d));
    }

    float s0 = 0.f, s1 = 0.f, s2 = 0.f, s3 = 0.f;
#pragma unroll
    for (int n = 0; n < 8; ++n) {
        c0[n][0] = exp2f(c0[n][0] - mx0);
        c0[n][1] = exp2f(c0[n][1] - mx0);
        c0[n][2] = exp2f(c0[n][2] - mx1);
        c0[n][3] = exp2f(c0[n][3] - mx1);
        c1[n][0] = exp2f(c1[n][0] - mx2);
        c1[n][1] = exp2f(c1[n][1] - mx2);
        c1[n][2] = exp2f(c1[n][2] - mx3);
        c1[n][3] = exp2f(c1[n][3] - mx3);
        s0 += c0[n][0] + c0[n][1];
        s1 += c0[n][2] + c0[n][3];
        s2 += c1[n][0] + c1[n][1];
        s3 += c1[n][2] + c1[n][3];
    }
#pragma unroll
    for (int d = 1; d <= 2; d <<= 1) {
        s0 += __shfl_xor_sync(0xffffffffu, s0, d);
        s1 += __shfl_xor_sync(0xffffffffu, s1, d);
        s2 += __shfl_xor_sync(0xffffffffu, s2, d);
        s3 += __shfl_xor_sync(0xffffffffu, s3, d);
    }
    float inv0 = 1.0f / s0, inv1 = 1.0f / s1;
    float inv2 = 1.0f / s2, inv3 = 1.0f / s3;

    // ---- stage unnormalized P over sQ (warp-private rows) -------------------
    float* sP = sQ;
#pragma unroll
    for (int n = 0; n < 8; ++n) {
        int col = n * 8 + 2 * tig;
        *(float2*)(sP + (r0 + g) * QSTRIDE + col)      = make_float2(c0[n][0], c0[n][1]);
        *(float2*)(sP + (r0 + g + 8) * QSTRIDE + col)  = make_float2(c0[n][2], c0[n][3]);
        *(float2*)(sP + (r0 + g + 16) * QSTRIDE + col) = make_float2(c1[n][0], c1[n][1]);
        *(float2*)(sP + (r0 + g + 24) * QSTRIDE + col) = make_float2(c1[n][2], c1[n][3]);
    }
    __syncwarp();

    // ---- V must be fully landed before PV ------------------------------------
    asm volatile("cp.async.wait_group 0;" ::: "memory");
    __syncthreads();

    // ---- O = P V : P exact (hi+lo), V raw fp32 as tf32 ----------------------
    float o0[8][4], o1[8][4];
#pragma unroll
    for (int d = 0; d < 8; ++d) {
#pragma unroll
        for (int j = 0; j < 4; ++j) { o0[d][j] = 0.f; o1[d][j] = 0.f; }
    }

#pragma unroll
    for (int ks = 0; ks < 8; ++ks) {
        const int kc = ks * 8 + tig;
        uint32_t ha0, la0, ha1, la1, ha2, la2, ha3, la3;
        uint32_t hc0, lc0, hc1, lc1, hc2, lc2, hc3, lc3;
        split_tf32(sP[(r0 + g) * QSTRIDE + kc],          ha0, la0);
        split_tf32(sP[(r0 + g + 8) * QSTRIDE + kc],      ha1, la1);
        split_tf32(sP[(r0 + g) * QSTRIDE + kc + 4],      ha2, la2);
        split_tf32(sP[(r0 + g + 8) * QSTRIDE + kc + 4],  ha3, la3);
        split_tf32(sP[(r0 + g + 16) * QSTRIDE + kc],     hc0, lc0);
        split_tf32(sP[(r0 + g + 24) * QSTRIDE + kc],     hc1, lc1);
        split_tf32(sP[(r0 + g + 16) * QSTRIDE + kc + 4], hc2, lc2);
        split_tf32(sP[(r0 + g + 24) * QSTRIDE + kc + 4], hc3, lc3);
#pragma unroll
        for (int dt = 0; dt < 8; ++dt) {
            uint32_t b0 = __float_as_uint(sKV[(ks * 8 + tig) * VSTRIDE + dt * 8 + g]);
            uint32_t b1 = __float_as_uint(sKV[(ks * 8 + tig + 4) * VSTRIDE + dt * 8 + g]);
            mma_tf32(o0[dt], ha0, ha1, ha2, ha3, b0, b1);
            mma_tf32(o0[dt], la0, la1, la2, la3, b0, b1);
            mma_tf32(o1[dt], hc0, hc1, hc2, hc3, b0, b1);
            mma_tf32(o1[dt], lc0, lc1, lc2, lc3, b0, b1);
        }
    }

    // ---- stage normalized O over sP (warp-private rows) ---------------------
    __syncwarp();
    float* sO = sQ;
#pragma unroll
    for (int dt = 0; dt < 8; ++dt) {
        int col = dt * 8 + 2 * tig;
        *(float2*)(sO + (r0 + g) * QSTRIDE + col)      = make_float2(o0[dt][0] * inv0, o0[dt][1] * inv0);
        *(float2*)(sO + (r0 + g + 8) * QSTRIDE + col)  = make_float2(o0[dt][2] * inv1, o0[dt][3] * inv1);
        *(float2*)(sO + (r0 + g + 16) * QSTRIDE + col) = make_float2(o1[dt][0] * inv2, o1[dt][1] * inv2);
        *(float2*)(sO + (r0 + g + 24) * QSTRIDE + col) = make_float2(o1[dt][2] * inv3, o1[dt][3] * inv3);
    }
    __syncthreads();

    // out[b*32768 + row*512 + ((h*64 + d - 32) & 511)], row-contiguous float4
    {
        float* ob = out + (size_t)b * 32768;
        const int cbase = h * 64 - 32;
        const int c4 = tid & 15;            // 16 float4 per row
        const int col = (cbase + 4 * c4) & 511;
#pragma unroll
        for (int it = 0; it < 16; ++it) {
            int row = (tid >> 4) + 4 * it;
            float4 val = *(const float4*)(sO + row * QSTRIDE + c4 * 4);
            *(float4*)(ob + row * 512 + col) = val;
        }
    }
}

extern "C" void kernel_launch(void* const* d_in, const int* in_sizes, int n_in,
                              void* d_out, int out_size) {
    const float* q     = (const float*)d_in[0];
    const float* k     = (const float*)d_in[1];
    const float* v     = (const float*)d_in[2];
    const float* table = (const float*)d_in[3];
    float* out = (float*)d_out;

    bias_precompute_kernel<<<32, 256>>>(table);

    const int smem_bytes = (SQ_FLOATS + SKV_FLOATS) * sizeof(float); // 35840 B
    cudaFuncSetAttribute(winattn_kernel,
                         cudaFuncAttributeMaxDynamicSharedMemorySize, smem_bytes);
    winattn_kernel<<<16384, 64, smem_bytes>>>(q, k, v, out);
}